// round 7
// baseline (speedup 1.0000x reference)
#include <cuda_runtime.h>
#include <cstdint>

// HashGridEncoding (16 levels, F=2, T=2^19, base 16, scale 1.5) fused with
// Linear(32 -> 64).  x:[8,131072,3] f32, table:[16,524288,2] f32,
// W:[64,32] f32, b:[64] f32 -> out:[8,131072,64] f32.

#define NLEVELS 16
#define TSIZE   (1u << 19)
#define TMASK   (TSIZE - 1u)
#define HP1     2654435761u
#define HP2     805459861u

// scale_l = f32(16*1.5^l - 1) computed exactly in double.
__constant__ float cScales[NLEVELS] = {
    15.0f, 23.0f, 35.0f, 53.0f, 80.0f, 120.5f, 181.25f, 272.375f,
    409.0625f, 614.09375f, 921.640625f, 1382.9609375f,
    2074.94140625f, 3112.912109375f, 4669.8681640625f, 7005.30224609375f };

// W packed as fp32 pairs: cWp[j*16 + i] = (W[j][2i], W[j][2i+1]); bias in cB.
// Filled per-launch via cudaMemcpyToSymbolAsync (D2D, graph-capturable).
__constant__ unsigned long long cWp[64 * 16];
__constant__ float cB[64];

__device__ __forceinline__ uint32_t umin32(uint32_t a, uint32_t b) { return a < b ? a : b; }

// packed fp32x2 fma: d = a*b + d (elementwise, exact fp32)
__device__ __forceinline__ void fma2(unsigned long long& d,
                                     unsigned long long a,
                                     unsigned long long b) {
    asm("fma.rn.f32x2 %0, %1, %2, %0;" : "+l"(d) : "l"(a), "l"(b));
}
__device__ __forceinline__ float2 u2f(unsigned long long v) {
    float2 r;
    asm("mov.b64 {%0, %1}, %2;" : "=f"(r.x), "=f"(r.y) : "l"(v));
    return r;
}

// One hashed level gather+interp. Returns (a0,a1).
__device__ __forceinline__ float2 hashed_level(const float4* __restrict__ tl4,
                                               const float2* __restrict__ tl2,
                                               float xn, float yn, float zn, float s)
{
    const float px = __fadd_rn(__fmul_rn(xn, s), 0.5f);
    const float py = __fadd_rn(__fmul_rn(yn, s), 0.5f);
    const float pz = __fadd_rn(__fmul_rn(zn, s), 0.5f);
    const float fx0 = floorf(px), fy0 = floorf(py), fz0 = floorf(pz);
    const float fx = __fadd_rn(px, -fx0);
    const float fy = __fadd_rn(py, -fy0);
    const float fz = __fadd_rn(pz, -fz0);
    const uint32_t x0 = (uint32_t)fx0;
    const uint32_t y0 = (uint32_t)fy0;
    const uint32_t z0 = (uint32_t)fz0;

    const float wx0 = 1.0f - fx, wx1 = fx;
    const float wy0 = 1.0f - fy, wy1 = fy;
    const float wz0 = 1.0f - fz, wz1 = fz;

    const uint32_t hy0 = y0 * HP1;
    const uint32_t hy1 = hy0 + HP1;
    const uint32_t hz0 = z0 * HP2;
    const uint32_t hz1 = hz0 + HP2;
    const uint32_t x1  = x0 + 1u;
    const bool xodd = (x0 & 1u) != 0u;

    const uint32_t hyz[4] = { hy0 ^ hz0, hy0 ^ hz1, hy1 ^ hz0, hy1 ^ hz1 };
    const float    wyz[4] = { wy0 * wz0, wy0 * wz1, wy1 * wz0, wy1 * wz1 };

    uint32_t i0s[4];
    #pragma unroll
    for (int r = 0; r < 4; ++r) i0s[r] = (x0 ^ hyz[r]) & TMASK;

    float4 v4[4];
    #pragma unroll
    for (int r = 0; r < 4; ++r) v4[r] = __ldg(tl4 + (i0s[r] >> 1));

    float2 vb[4];
    if (xodd) {
        #pragma unroll
        for (int r = 0; r < 4; ++r)
            vb[r] = __ldg(tl2 + ((x1 ^ hyz[r]) & TMASK));
    }

    float a0 = 0.0f, a1 = 0.0f;
    #pragma unroll
    for (int r = 0; r < 4; ++r) {
        const bool hi = (i0s[r] & 1u) != 0u;
        const float c0x = hi ? v4[r].z : v4[r].x;
        const float c0y = hi ? v4[r].w : v4[r].y;
        const float ox  = hi ? v4[r].x : v4[r].z;
        const float oy  = hi ? v4[r].y : v4[r].w;
        const float c1x = xodd ? vb[r].x : ox;
        const float c1y = xodd ? vb[r].y : oy;

        const float w0 = wx0 * wyz[r];
        const float w1 = wx1 * wyz[r];
        a0 = fmaf(w0, c0x, a0);
        a1 = fmaf(w0, c0y, a1);
        a0 = fmaf(w1, c1x, a0);
        a1 = fmaf(w1, c1y, a1);
    }
    return make_float2(a0, a1);
}

__global__ __launch_bounds__(128, 5)
void hashgrid_fused_kernel(const float* __restrict__ x,
                           const float* __restrict__ table,
                           float* __restrict__ out,
                           int P)
{
    // Union buffer (32KB):
    //  - gather phase: enc rows, thread t at float4 slots [t*9 + k], k=0..7
    //    (thread-private round-trip; no sync needed).
    //  - output phase: transpose rows, point t at slots [t*16 + ((j4+t)&15)]
    //    (swizzled -> conflict-free STS.128/LDS.128).
    __shared__ float4 sBuf[2048];

    const int tid = threadIdx.x;
    const int blockBase = blockIdx.x * 128;
    const int p  = blockBase + tid;
    const int pc = (p < P) ? p : (P - 1);

    const float xn = __fmul_rn(__fadd_rn(x[3 * pc + 0], 1.0f), 0.5f);
    const float yn = __fmul_rn(__fadd_rn(x[3 * pc + 1], 1.0f), 0.5f);
    const float zn = __fmul_rn(__fadd_rn(x[3 * pc + 2], 1.0f), 0.5f);

    const float2* __restrict__ tbl2 = reinterpret_cast<const float2*>(table);
    const float4* __restrict__ tbl4 = reinterpret_cast<const float4*>(table);

    // ---- dense levels 0..3 (fully unrolled, compile-time res) ----
    {
        const uint32_t RES_D[4] = { 16u, 24u, 36u, 54u };
        const float    SC_D[4]  = { 15.0f, 23.0f, 35.0f, 53.0f };
        float keep0 = 0.0f, keep1 = 0.0f;
        #pragma unroll
        for (int l = 0; l < 4; ++l) {
            const float s  = SC_D[l];
            const float px = __fadd_rn(__fmul_rn(xn, s), 0.5f);
            const float py = __fadd_rn(__fmul_rn(yn, s), 0.5f);
            const float pz = __fadd_rn(__fmul_rn(zn, s), 0.5f);
            const float fx0 = floorf(px), fy0 = floorf(py), fz0 = floorf(pz);
            const float fx = __fadd_rn(px, -fx0);
            const float fy = __fadd_rn(py, -fy0);
            const float fz = __fadd_rn(pz, -fz0);
            const uint32_t x0 = (uint32_t)fx0;
            const uint32_t y0 = (uint32_t)fy0;
            const uint32_t z0 = (uint32_t)fz0;

            const float wx0 = 1.0f - fx, wx1 = fx;
            const float wy0 = 1.0f - fy, wy1 = fy;
            const float wz0 = 1.0f - fz, wz1 = fz;

            const uint32_t R   = RES_D[l];
            const uint32_t cx0 = umin32(x0, R - 1u);
            const bool d1      = (x0 < R - 1u);
            const bool xodd    = (x0 & 1u) != 0u;
            const uint32_t iy0 = umin32(y0,      R - 1u) * R;
            const uint32_t iy1 = umin32(y0 + 1u, R - 1u) * R;
            const uint32_t iz0 = umin32(z0,      R - 1u) * (R * R);
            const uint32_t iz1 = umin32(z0 + 1u, R - 1u) * (R * R);

            const uint32_t byz[4] = { iy0 + iz0, iy0 + iz1, iy1 + iz0, iy1 + iz1 };
            const float    wyz[4] = { wy0 * wz0, wy0 * wz1, wy1 * wz0, wy1 * wz1 };

            const float2* tl2 = tbl2 + (size_t)l * TSIZE;
            const float4* tl4 = tbl4 + (size_t)l * (TSIZE / 2);

            uint32_t i0s[4];
            #pragma unroll
            for (int r = 0; r < 4; ++r) i0s[r] = cx0 + byz[r];

            float4 v4[4];
            #pragma unroll
            for (int r = 0; r < 4; ++r) v4[r] = __ldg(tl4 + (i0s[r] >> 1));

            const bool need2 = d1 && xodd;
            float2 vb[4];
            if (need2) {
                #pragma unroll
                for (int r = 0; r < 4; ++r) vb[r] = __ldg(tl2 + (i0s[r] + 1u));
            }

            float a0 = 0.0f, a1 = 0.0f;
            #pragma unroll
            for (int r = 0; r < 4; ++r) {
                const bool hi = (i0s[r] & 1u) != 0u;
                const float c0x = hi ? v4[r].z : v4[r].x;
                const float c0y = hi ? v4[r].w : v4[r].y;
                const float ox  = hi ? vb[r].x : v4[r].z;
                const float oy  = hi ? vb[r].y : v4[r].w;
                const float c1x = d1 ? ox : c0x;
                const float c1y = d1 ? oy : c0y;

                const float w0 = wx0 * wyz[r];
                const float w1 = wx1 * wyz[r];
                a0 = fmaf(w0, c0x, a0);
                a1 = fmaf(w0, c0y, a1);
                a0 = fmaf(w1, c1x, a0);
                a1 = fmaf(w1, c1y, a1);
            }
            if ((l & 1) == 0) { keep0 = a0; keep1 = a1; }
            else sBuf[tid * 9 + (l >> 1)] = make_float4(keep0, keep1, a0, a1);
        }
    }

    // ---- hashed levels 4..15: rolled loop over 6 level-pairs (low regs) ----
    #pragma unroll 1
    for (int lp = 2; lp < 8; ++lp) {
        const int l0 = 2 * lp;
        const float2 rA = hashed_level(tbl4 + (size_t)l0 * (TSIZE / 2),
                                       tbl2 + (size_t)l0 * TSIZE,
                                       xn, yn, zn, cScales[l0]);
        const float2 rB = hashed_level(tbl4 + (size_t)(l0 + 1) * (TSIZE / 2),
                                       tbl2 + (size_t)(l0 + 1) * TSIZE,
                                       xn, yn, zn, cScales[l0 + 1]);
        sBuf[tid * 9 + lp] = make_float4(rA.x, rA.y, rB.x, rB.y);
    }

    // ---- load own enc back into registers as 16 packed fp32 pairs
    //      (thread-private smem round-trip: program order, no sync) ----
    unsigned long long encp[16];
    #pragma unroll
    for (int k = 0; k < 8; ++k) {
        const ulonglong2 v = *reinterpret_cast<const ulonglong2*>(&sBuf[tid * 9 + k]);
        encp[2 * k + 0] = v.x;
        encp[2 * k + 1] = v.y;
    }

    __syncthreads();   // everyone holds enc in regs before sBuf is reused

    // ---- own-point Linear(32 -> 64): W from __constant__ (uniform LDCU,
    //      bypasses L1), enc in registers, packed fp32x2 FMA. ----
    #pragma unroll 1
    for (int jc = 0; jc < 8; ++jc) {
        unsigned long long A[8];
        #pragma unroll
        for (int jj = 0; jj < 8; ++jj) A[jj] = 0ull;

        const int jb = jc * 8;
        #pragma unroll
        for (int i = 0; i < 16; ++i) {
            #pragma unroll
            for (int jj = 0; jj < 8; ++jj)
                fma2(A[jj], encp[i], cWp[(jb + jj) * 16 + i]);
        }

        float o[8];
        #pragma unroll
        for (int jj = 0; jj < 8; ++jj) {
            const float2 f = u2f(A[jj]);
            o[jj] = cB[jb + jj] + f.x + f.y;
        }
        // swizzled transpose store (conflict-free STS.128)
        const int s0 = (jc * 2 + tid) & 15;
        const int s1 = (jc * 2 + 1 + tid) & 15;
        sBuf[tid * 16 + s0] = make_float4(o[0], o[1], o[2], o[3]);
        sBuf[tid * 16 + s1] = make_float4(o[4], o[5], o[6], o[7]);
    }

    __syncwarp();   // transpose rows are per-warp-private

    // ---- coalesced copy-out: warp streams its 32 points' rows (128B/lane-it) ----
    const int lane  = tid & 31;
    const int wbase = tid & ~31;
    float4* __restrict__ outG4 = reinterpret_cast<float4*>(out);

    #pragma unroll
    for (int it = 0; it < 16; ++it) {
        const int linear = it * 32 + lane;          // 512 float4 per warp
        const int pl = wbase + (linear >> 4);       // local point
        const int j4 = linear & 15;                 // output float4 index
        const float4 v = sBuf[pl * 16 + ((j4 + pl) & 15)];
        const int gp = blockBase + pl;
        if (gp < P)
            outG4[(size_t)gp * 16 + j4] = v;        // 512B contiguous per warp-it
    }
}

extern "C" void kernel_launch(void* const* d_in, const int* in_sizes, int n_in,
                              void* d_out, int out_size)
{
    const float* x     = (const float*)d_in[0];
    const float* table = (const float*)d_in[1];
    const float* W     = (const float*)d_in[2];
    const float* b     = (const float*)d_in[3];
    float* out = (float*)d_out;

    // W rows are 32 floats = 16 fp32-pairs; same memory layout as cWp.
    cudaMemcpyToSymbolAsync(cWp, W, 64 * 32 * sizeof(float), 0,
                            cudaMemcpyDeviceToDevice, 0);
    cudaMemcpyToSymbolAsync(cB, b, 64 * sizeof(float), 0,
                            cudaMemcpyDeviceToDevice, 0);

    const int P    = in_sizes[0] / 3;          // 1,048,576 points
    const int grid = (P + 127) / 128;
    hashgrid_fused_kernel<<<grid, 128>>>(x, table, out, P);
}